// round 2
// baseline (speedup 1.0000x reference)
#include <cuda_runtime.h>

#define B 128
#define K 17
#define HW 9216          // 96*96
#define NVEC (HW/4)      // 2304
#define TOPK 8
#define THREADS1 256
#define NBLOCKS (B * K)  // 2176

__device__ float g_per_joint[B * K];
__device__ unsigned int g_counter = 0;

__global__ void __launch_bounds__(THREADS1, 4)
mse_ohkm_fused_kernel(const float* __restrict__ pred,
                      const float* __restrict__ gt,
                      const float* __restrict__ tw,
                      float* __restrict__ out) {
    const int bk = blockIdx.x;                    // 0 .. B*K-1
    const int tid = threadIdx.x;
    const float4* __restrict__ p = reinterpret_cast<const float4*>(pred + (size_t)bk * HW);
    const float4* __restrict__ g = reinterpret_cast<const float4*>(gt   + (size_t)bk * HW);
    const float w = tw[bk];

    float acc = 0.0f;
    #pragma unroll
    for (int i = tid; i < NVEC; i += THREADS1) {
        float4 a = p[i];
        float4 b = g[i];
        float d0 = (a.x - b.x) * w;
        float d1 = (a.y - b.y) * w;
        float d2 = (a.z - b.z) * w;
        float d3 = (a.w - b.w) * w;
        acc += d0 * d0 + d1 * d1 + d2 * d2 + d3 * d3;
    }

    // block reduce
    #pragma unroll
    for (int off = 16; off > 0; off >>= 1)
        acc += __shfl_down_sync(0xFFFFFFFFu, acc, off);

    __shared__ float warp_sums[THREADS1 / 32];
    const int lane = tid & 31;
    const int wid  = tid >> 5;
    if (lane == 0) warp_sums[wid] = acc;
    __syncthreads();

    if (wid == 0) {
        float v = (lane < THREADS1 / 32) ? warp_sums[lane] : 0.0f;
        #pragma unroll
        for (int off = 4; off > 0; off >>= 1)
            v += __shfl_down_sync(0xFFFFFFFFu, v, off);
        if (lane == 0) g_per_joint[bk] = v * (1.0f / (float)HW);
    }

    // ---- last-block-done: fold the OHKM top-k into this kernel ----
    __shared__ unsigned int is_last;
    __threadfence();   // make g_per_joint[bk] visible before counting
    if (tid == 0) {
        unsigned int old = atomicAdd(&g_counter, 1u);
        is_last = (old == (unsigned int)(NBLOCKS - 1)) ? 1u : 0u;
    }
    __syncthreads();
    if (!is_last) return;

    // Last block: per-joint values for ALL (b,k) are globally visible and
    // hot in L2. Threads 0..127 each handle one sample.
    __shared__ float sh[B];
    float s = 0.0f;
    if (tid < B) {
        float v[K];
        #pragma unroll
        for (int i = 0; i < K; i++)
            v[i] = g_per_joint[tid * K + i];

        #pragma unroll
        for (int t = 0; t < TOPK; t++) {
            float m = v[0];
            int mi = 0;
            #pragma unroll
            for (int i = 1; i < K; i++) {
                if (v[i] > m) { m = v[i]; mi = i; }
            }
            s += m;
            v[mi] = -3.4e38f;
        }
        sh[tid] = s;
    }
    __syncthreads();

    #pragma unroll
    for (int stride = B / 2; stride > 0; stride >>= 1) {
        if (tid < stride) sh[tid] += sh[tid + stride];
        __syncthreads();
    }
    if (tid == 0) {
        out[0] = sh[0] * (1.0f / (float)(B * TOPK));
        g_counter = 0u;   // reset for the next (graph-replayed) launch
    }
}

extern "C" void kernel_launch(void* const* d_in, const int* in_sizes, int n_in,
                              void* d_out, int out_size) {
    const float* pred = (const float*)d_in[0];   // output [B,K,H,W]
    const float* gt   = (const float*)d_in[1];   // target [B,K,H,W]
    const float* tw   = (const float*)d_in[2];   // target_weight [B,K,1]
    float* out = (float*)d_out;

    mse_ohkm_fused_kernel<<<NBLOCKS, THREADS1>>>(pred, gt, tw, out);
}

// round 3
// speedup vs baseline: 1.0261x; 1.0261x over previous
#include <cuda_runtime.h>

#define B 128
#define K 17
#define HW 9216          // 96*96
#define NVEC (HW/4)      // 2304
#define TOPK 8
#define THREADS1 256

__device__ float g_per_joint[B * K];

__global__ void __launch_bounds__(THREADS1, 4)
mse_per_joint_kernel(const float* __restrict__ pred,
                     const float* __restrict__ gt,
                     const float* __restrict__ tw) {
    const int bk = blockIdx.x;                    // 0 .. B*K-1
    const float4* __restrict__ p = reinterpret_cast<const float4*>(pred + (size_t)bk * HW);
    const float4* __restrict__ g = reinterpret_cast<const float4*>(gt   + (size_t)bk * HW);
    const float w = tw[bk];

    float acc = 0.0f;
    #pragma unroll
    for (int j = 0; j < NVEC / THREADS1; j++) {   // 9 iterations, fully unrolled
        const int i = threadIdx.x + j * THREADS1;
        float4 a = p[i];
        float4 b = g[i];
        float d0 = (a.x - b.x) * w;
        float d1 = (a.y - b.y) * w;
        float d2 = (a.z - b.z) * w;
        float d3 = (a.w - b.w) * w;
        acc += d0 * d0 + d1 * d1 + d2 * d2 + d3 * d3;
    }

    // warp reduce
    #pragma unroll
    for (int off = 16; off > 0; off >>= 1)
        acc += __shfl_down_sync(0xFFFFFFFFu, acc, off);

    __shared__ float warp_sums[THREADS1 / 32];
    const int lane = threadIdx.x & 31;
    const int wid  = threadIdx.x >> 5;
    if (lane == 0) warp_sums[wid] = acc;
    __syncthreads();

    if (wid == 0) {
        float v = (lane < THREADS1 / 32) ? warp_sums[lane] : 0.0f;
        #pragma unroll
        for (int off = 4; off > 0; off >>= 1)
            v += __shfl_down_sync(0xFFFFFFFFu, v, off);
        if (lane == 0) g_per_joint[bk] = v * (1.0f / (float)HW);
    }
}

__global__ void __launch_bounds__(B, 1)
ohkm_topk_kernel(float* __restrict__ out) {
    const int b = threadIdx.x;   // one thread per sample

    // Register-resident top-8 via insertion network (NO dynamic indexing ->
    // no local-memory spill). t[] stays sorted descending.
    float t[TOPK];
    #pragma unroll
    for (int j = 0; j < TOPK; j++) t[j] = -3.4e38f;

    #pragma unroll
    for (int i = 0; i < K; i++) {
        float x = g_per_joint[b * K + i];
        #pragma unroll
        for (int j = 0; j < TOPK; j++) {
            float old = t[j];
            bool gt = x > old;
            t[j] = gt ? x : old;
            x    = gt ? old : x;
        }
    }

    float s = 0.0f;
    #pragma unroll
    for (int j = 0; j < TOPK; j++) s += t[j];

    __shared__ float sh[B];
    sh[b] = s;
    __syncthreads();
    #pragma unroll
    for (int stride = B / 2; stride > 0; stride >>= 1) {
        if (b < stride) sh[b] += sh[b + stride];
        __syncthreads();
    }
    if (b == 0)
        out[0] = sh[0] * (1.0f / (float)(B * TOPK));
}

extern "C" void kernel_launch(void* const* d_in, const int* in_sizes, int n_in,
                              void* d_out, int out_size) {
    const float* pred = (const float*)d_in[0];   // output [B,K,H,W]
    const float* gt   = (const float*)d_in[1];   // target [B,K,H,W]
    const float* tw   = (const float*)d_in[2];   // target_weight [B,K,1]
    float* out = (float*)d_out;

    mse_per_joint_kernel<<<B * K, THREADS1>>>(pred, gt, tw);
    ohkm_topk_kernel<<<1, B>>>(out);
}